// round 5
// baseline (speedup 1.0000x reference)
#include <cuda_runtime.h>
#include <cuda_bf16.h>
#include <cstdint>
#include <math.h>

// Problem dims
#define BB   4
#define SS   2048
#define DD   1024
#define HH   16
#define FF   4096
#define MROWS (BB*SS)          // 8192
#define NBLK (SS/64)           // 32

// ---------------- scratch (device globals; no allocation allowed) ----------
__device__ float g_x1[MROWS*DD];   // LN1 output; reused as attention O
__device__ float g_q [MROWS*DD];   // Q; reused as x2 (LN2 output)
__device__ float g_k [MROWS*DD];
__device__ float g_v [MROWS*DD];
__device__ float g_h [MROWS*DD];   // residual stream after attention
__device__ float g_ff[MROWS*FF];   // GELU MLP intermediate
// transposed weights (N-major "Bt[n][k]" for the mma B operand)
__device__ float g_wqT[DD*DD];
__device__ float g_wkT[DD*DD];
__device__ float g_wvT[DD*DD];
__device__ float g_woT[DD*DD];
__device__ float g_w1T[FF*DD];     // [4096][1024]
__device__ float g_w2T[DD*FF];     // [1024][4096]

// ---------------- PTX helpers (base-target-safe only) -----------------------
__device__ __forceinline__ uint32_t smem_u32(const void* p) {
    uint32_t a;
    asm("{ .reg .u64 t; cvta.to.shared.u64 t, %1; cvt.u32.u64 %0, t; }"
        : "=r"(a) : "l"(p));
    return a;
}
__device__ __forceinline__ void cp16(uint32_t dst, const void* src) {
    asm volatile("cp.async.cg.shared.global [%0], [%1], 16;"
                 :: "r"(dst), "l"(src) : "memory");
}
#define CP_COMMIT() asm volatile("cp.async.commit_group;" ::: "memory")
#define CP_WAIT(n)  asm volatile("cp.async.wait_group %0;" :: "n"(n) : "memory")

__device__ __forceinline__ void mma_tf32(float* d, const uint32_t* a,
                                         const uint32_t* b) {
    asm volatile(
        "mma.sync.aligned.m16n8k8.row.col.f32.tf32.tf32.f32 "
        "{%0,%1,%2,%3}, {%4,%5,%6,%7}, {%8,%9}, {%0,%1,%2,%3};"
        : "+f"(d[0]), "+f"(d[1]), "+f"(d[2]), "+f"(d[3])
        : "r"(a[0]), "r"(a[1]), "r"(a[2]), "r"(a[3]), "r"(b[0]), "r"(b[1]));
}

// ---------------- LayerNorm (one block per row, D=1024) --------------------
__global__ __launch_bounds__(256) void ln_kernel(
    const float* __restrict__ x, const float* __restrict__ g,
    const float* __restrict__ b, float* __restrict__ y)
{
    __shared__ float rs[8], rq[8];
    int row = blockIdx.x, t = threadIdx.x;
    const float4* xr = reinterpret_cast<const float4*>(x) + (size_t)row * 256;
    float4 v = xr[t];
    float s = v.x + v.y + v.z + v.w;
    float q = fmaf(v.x, v.x, fmaf(v.y, v.y, fmaf(v.z, v.z, v.w * v.w)));
    #pragma unroll
    for (int o = 16; o; o >>= 1) {
        s += __shfl_xor_sync(0xffffffffu, s, o);
        q += __shfl_xor_sync(0xffffffffu, q, o);
    }
    if ((t & 31) == 0) { rs[t >> 5] = s; rq[t >> 5] = q; }
    __syncthreads();
    float ts = 0.f, tq = 0.f;
    #pragma unroll
    for (int i = 0; i < 8; i++) { ts += rs[i]; tq += rq[i]; }
    float mean = ts * (1.0f / 1024.0f);
    float var  = tq * (1.0f / 1024.0f) - mean * mean;
    float inv  = rsqrtf(var + 1e-5f);
    float4 gg = reinterpret_cast<const float4*>(g)[t];
    float4 bb = reinterpret_cast<const float4*>(b)[t];
    float4 o4;
    o4.x = (v.x - mean) * inv * gg.x + bb.x;
    o4.y = (v.y - mean) * inv * gg.y + bb.y;
    o4.z = (v.z - mean) * inv * gg.z + bb.z;
    o4.w = (v.w - mean) * inv * gg.w + bb.w;
    reinterpret_cast<float4*>(y)[(size_t)row * 256 + t] = o4;
}

// ---------------- weight transpose: in[K][N] -> out[N][K] -------------------
__global__ __launch_bounds__(256) void transpose_kernel(
    const float* __restrict__ in, float* __restrict__ out, int K, int N)
{
    __shared__ float t[32][33];
    int tx = threadIdx.x, ty = threadIdx.y;        // 32 x 8
    int bn = blockIdx.x * 32, bk = blockIdx.y * 32;
    #pragma unroll
    for (int i = 0; i < 4; i++)
        t[ty + 8 * i][tx] = in[(size_t)(bk + ty + 8 * i) * N + bn + tx];
    __syncthreads();
    #pragma unroll
    for (int i = 0; i < 4; i++)
        out[(size_t)(bn + ty + 8 * i) * K + bk + tx] = t[tx][ty + 8 * i];
}

// ---------------- tf32 mma.sync GEMM, 3-stage cp.async pipeline -------------
// C[M,N] = A[M,K] @ Bt[N,K]^T + bias, epilogue
// EPI: 0 = bias, 1 = bias + residual, 2 = bias + exact GELU
// CTA tile 128x128, K-chunk 32, STAGES=3, one __syncthreads per chunk.
#define LDS36 36
#define TILE_F (128 * LDS36)               // 4608 floats per operand tile
#define STAGES 3
#define SMEM_BYTES (STAGES * 2 * TILE_F * 4)   // 110592 bytes

template<int EPI>
__global__ __launch_bounds__(256, 2) void tgemm(
    const float* __restrict__ A, const float* __restrict__ Bt,
    const float* __restrict__ bias, const float* __restrict__ res,
    float* __restrict__ C, int M, int N, int K)
{
    extern __shared__ float smf[];
    const uint32_t sbase = smem_u32(smf);
    const int tid  = threadIdx.x;
    const int wid  = tid >> 5;
    const int lane = tid & 31;
    const int g    = lane >> 2;        // groupID
    const int c    = lane & 3;         // threadID_in_group
    const int warp_m = wid & 3;        // 4 warps down M (32 rows each)
    const int warp_n = wid >> 2;       // 2 warps across N (64 cols each)
    const int bm = blockIdx.y * 128;
    const int bn = blockIdx.x * 128;

    // loader coords: 4 float4 per operand per thread per chunk
    const int r0 = tid >> 3;           // rows r0, r0+32, r0+64, r0+96
    const int u0 = tid & 7;            // 16B slot in the 32-float k-chunk

    const float* aptr = A  + (size_t)(bm + r0) * K + u0 * 4;
    const float* bptr = Bt + (size_t)(bn + r0) * K + u0 * 4;
    const uint32_t soff0 = (uint32_t)(r0 * LDS36 + u0 * 4) * 4u;

    float acc[2][8][4];
    #pragma unroll
    for (int i = 0; i < 2; i++)
        #pragma unroll
        for (int j = 0; j < 8; j++)
            #pragma unroll
            for (int r = 0; r < 4; r++) acc[i][j][r] = 0.f;

    const int NK = K >> 5;

    // issue chunk `kc` into stage `s`
    auto issue = [&](int kc, int s) {
        const uint32_t stA = sbase + (uint32_t)(s * 2) * TILE_F * 4u;
        const uint32_t stB = stA + TILE_F * 4u;
        const float* ap = aptr + (size_t)kc * 32;
        const float* bp = bptr + (size_t)kc * 32;
        #pragma unroll
        for (int t = 0; t < 4; t++) {
            const uint32_t so = soff0 + (uint32_t)(t * 32 * LDS36) * 4u;
            cp16(stA + so, ap + (size_t)(t * 32) * K);
            cp16(stB + so, bp + (size_t)(t * 32) * K);
        }
    };

    // prologue: stages 0 and 1
    issue(0, 0); CP_COMMIT();
    issue(1, 1); CP_COMMIT();

    int s_rd = 0, s_wr = 2;
    for (int k = 0; k < NK; k++) {
        CP_WAIT(1);
        __syncthreads();
        if (k + 2 < NK) issue(k + 2, s_wr);
        CP_COMMIT();
        s_wr = (s_wr == STAGES - 1) ? 0 : s_wr + 1;

        const float* As = smf + s_rd * 2 * TILE_F;
        const float* Bs = As + TILE_F;
        s_rd = (s_rd == STAGES - 1) ? 0 : s_rd + 1;

        #pragma unroll
        for (int ks = 0; ks < 4; ks++) {
            const int k0 = ks * 8;
            uint32_t afr[2][4], bfr[8][2];
            #pragma unroll
            for (int im = 0; im < 2; im++) {
                const int r = warp_m * 32 + im * 16;
                afr[im][0] = __float_as_uint(As[(r + g    ) * LDS36 + k0 + c    ]);
                afr[im][1] = __float_as_uint(As[(r + g + 8) * LDS36 + k0 + c    ]);
                afr[im][2] = __float_as_uint(As[(r + g    ) * LDS36 + k0 + c + 4]);
                afr[im][3] = __float_as_uint(As[(r + g + 8) * LDS36 + k0 + c + 4]);
            }
            #pragma unroll
            for (int in = 0; in < 8; in++) {
                const int n = warp_n * 64 + in * 8;
                bfr[in][0] = __float_as_uint(Bs[(n + g) * LDS36 + k0 + c    ]);
                bfr[in][1] = __float_as_uint(Bs[(n + g) * LDS36 + k0 + c + 4]);
            }
            #pragma unroll
            for (int im = 0; im < 2; im++)
                #pragma unroll
                for (int in = 0; in < 8; in++)
                    mma_tf32(acc[im][in], afr[im], bfr[in]);
        }
    }

    // ---- epilogue ----
    #pragma unroll
    for (int im = 0; im < 2; im++) {
        #pragma unroll
        for (int half = 0; half < 2; half++) {
            const int row = bm + warp_m * 32 + im * 16 + g + half * 8;
            #pragma unroll
            for (int in = 0; in < 8; in++) {
                const int col = bn + warp_n * 64 + in * 8 + 2 * c;
                float v0 = acc[im][in][half * 2 + 0] + bias[col];
                float v1 = acc[im][in][half * 2 + 1] + bias[col + 1];
                if (EPI == 1) {
                    const float2 rr = *reinterpret_cast<const float2*>(
                        &res[(size_t)row * N + col]);
                    v0 += rr.x; v1 += rr.y;
                }
                if (EPI == 2) {
                    v0 = 0.5f * v0 * (1.0f + erff(v0 * 0.70710678118654752f));
                    v1 = 0.5f * v1 * (1.0f + erff(v1 * 0.70710678118654752f));
                }
                float2 o2 = make_float2(v0, v1);
                *reinterpret_cast<float2*>(&C[(size_t)row * N + col]) = o2;
            }
        }
    }
}

// ---------------- block-sparse attention (one CTA per (b,h,block)) ---------
__global__ __launch_bounds__(256) void attention_kernel(
    const float* __restrict__ Q, const float* __restrict__ K,
    const float* __restrict__ V, float* __restrict__ O,
    float* __restrict__ W)
{
    __shared__ float qs[64][65];
    __shared__ float ks[64][65];
    int tid = threadIdx.x;
    int blk = blockIdx.x;                    // b*512 + h*32 + n
    int n = blk & 31, hh = (blk >> 5) & 15, b = blk >> 9;
    size_t base = ((size_t)(b * SS + n * 64)) * DD + hh * 64;

    for (int i = tid; i < 4096; i += 256) {
        int r = i >> 6, c = i & 63;
        qs[r][c] = Q[base + (size_t)r * DD + c] * 0.125f;  // 1/sqrt(64)
        ks[r][c] = K[base + (size_t)r * DD + c];
    }
    __syncthreads();

    int qi  = tid >> 2;
    int kj0 = (tid & 3) << 4;
    float w[16];
    #pragma unroll
    for (int j = 0; j < 16; j++) {
        float acc = 0.f;
        #pragma unroll
        for (int d = 0; d < 64; d++)
            acc = fmaf(qs[qi][d], ks[kj0 + j][d], acc);
        w[j] = acc;
    }
    float m = w[0];
    #pragma unroll
    for (int j = 1; j < 16; j++) m = fmaxf(m, w[j]);
    m = fmaxf(m, __shfl_xor_sync(0xffffffffu, m, 1));
    m = fmaxf(m, __shfl_xor_sync(0xffffffffu, m, 2));
    float s = 0.f;
    #pragma unroll
    for (int j = 0; j < 16; j++) { w[j] = __expf(w[j] - m); s += w[j]; }
    s += __shfl_xor_sync(0xffffffffu, s, 1);
    s += __shfl_xor_sync(0xffffffffu, s, 2);
    float inv = 1.0f / s;
    #pragma unroll
    for (int j = 0; j < 16; j++) w[j] *= inv;

    if (W) {
        float* wout = W + (size_t)blk * 4096 + qi * 64 + kj0;
        #pragma unroll
        for (int j = 0; j < 16; j++) wout[j] = w[j];
    }

    __syncthreads();
    for (int i = tid; i < 4096; i += 256) {
        int r = i >> 6, c = i & 63;
        qs[r][c] = V[base + (size_t)r * DD + c];
    }
    __syncthreads();

    #pragma unroll
    for (int dc = 0; dc < 4; dc++) {
        float p[16];
        #pragma unroll
        for (int jj = 0; jj < 16; jj++) {
            int d = dc * 16 + jj;
            float acc = 0.f;
            #pragma unroll
            for (int j = 0; j < 16; j++)
                acc = fmaf(w[j], qs[kj0 + j][d], acc);
            p[jj] = acc;
        }
        #pragma unroll
        for (int jj = 0; jj < 16; jj++) {
            p[jj] += __shfl_xor_sync(0xffffffffu, p[jj], 1);
            p[jj] += __shfl_xor_sync(0xffffffffu, p[jj], 2);
        }
        if ((tid & 3) == dc) {
            #pragma unroll
            for (int jj = 0; jj < 16; jj++)
                O[base + (size_t)qi * DD + dc * 16 + jj] = p[jj];
        }
    }
}

// ---------------- host launcher ---------------------------------------------
extern "C" void kernel_launch(void* const* d_in, const int* in_sizes, int n_in,
                              void* d_out, int out_size)
{
    const float* hidden = (const float*)d_in[0];
    const float* ln1_g  = (const float*)d_in[1];
    const float* ln1_b  = (const float*)d_in[2];
    const float* ln2_g  = (const float*)d_in[3];
    const float* ln2_b  = (const float*)d_in[4];
    const float* wq = (const float*)d_in[5];  const float* bq = (const float*)d_in[6];
    const float* wk = (const float*)d_in[7];  const float* bk = (const float*)d_in[8];
    const float* wv = (const float*)d_in[9];  const float* bv = (const float*)d_in[10];
    const float* wo = (const float*)d_in[11]; const float* bo = (const float*)d_in[12];
    const float* w1 = (const float*)d_in[13]; const float* b1 = (const float*)d_in[14];
    const float* w2 = (const float*)d_in[15]; const float* b2 = (const float*)d_in[16];
    float* out = (float*)d_out;

    float *x1, *q, *k, *v, *h, *ff;
    float *wqT, *wkT, *wvT, *woT, *w1T, *w2T;
    cudaGetSymbolAddress((void**)&x1, g_x1);
    cudaGetSymbolAddress((void**)&q,  g_q);
    cudaGetSymbolAddress((void**)&k,  g_k);
    cudaGetSymbolAddress((void**)&v,  g_v);
    cudaGetSymbolAddress((void**)&h,  g_h);
    cudaGetSymbolAddress((void**)&ff, g_ff);
    cudaGetSymbolAddress((void**)&wqT, g_wqT);
    cudaGetSymbolAddress((void**)&wkT, g_wkT);
    cudaGetSymbolAddress((void**)&wvT, g_wvT);
    cudaGetSymbolAddress((void**)&woT, g_woT);
    cudaGetSymbolAddress((void**)&w1T, g_w1T);
    cudaGetSymbolAddress((void**)&w2T, g_w2T);

    cudaFuncSetAttribute(tgemm<0>, cudaFuncAttributeMaxDynamicSharedMemorySize, SMEM_BYTES);
    cudaFuncSetAttribute(tgemm<1>, cudaFuncAttributeMaxDynamicSharedMemorySize, SMEM_BYTES);
    cudaFuncSetAttribute(tgemm<2>, cudaFuncAttributeMaxDynamicSharedMemorySize, SMEM_BYTES);

    const int MAIN_ELEMS = MROWS * DD;                 // 8388608
    const int ATTW_ELEMS = BB * HH * NBLK * 64 * 64;   // 8388608
    float* attw = (out_size >= MAIN_ELEMS + ATTW_ELEMS) ? out + MAIN_ELEMS
                                                        : nullptr;

    dim3 tb(32, 8);
    transpose_kernel<<<dim3(DD/32, DD/32), tb>>>(wq, wqT, DD, DD);
    transpose_kernel<<<dim3(DD/32, DD/32), tb>>>(wk, wkT, DD, DD);
    transpose_kernel<<<dim3(DD/32, DD/32), tb>>>(wv, wvT, DD, DD);
    transpose_kernel<<<dim3(DD/32, DD/32), tb>>>(wo, woT, DD, DD);
    transpose_kernel<<<dim3(FF/32, DD/32), tb>>>(w1, w1T, DD, FF);
    transpose_kernel<<<dim3(DD/32, FF/32), tb>>>(w2, w2T, FF, DD);

    dim3 gD(DD / 128, MROWS / 128);   // (8, 64)
    dim3 gF(FF / 128, MROWS / 128);   // (32, 64)

    // x1 = LN1(hidden)
    ln_kernel<<<MROWS, 256>>>(hidden, ln1_g, ln1_b, x1);
    // q/k/v = x1 @ w{q,k,v} + b
    tgemm<0><<<gD, 256, SMEM_BYTES>>>(x1, wqT, bq, nullptr, q, MROWS, DD, DD);
    tgemm<0><<<gD, 256, SMEM_BYTES>>>(x1, wkT, bk, nullptr, k, MROWS, DD, DD);
    tgemm<0><<<gD, 256, SMEM_BYTES>>>(x1, wvT, bv, nullptr, v, MROWS, DD, DD);
    // block attention: O into x1; optional attn_w out
    attention_kernel<<<BB * HH * NBLK, 256>>>(q, k, v, x1, attw);
    // h = hidden + O @ wo + bo
    tgemm<1><<<gD, 256, SMEM_BYTES>>>(x1, woT, bo, hidden, h, MROWS, DD, DD);
    // x2 = LN2(h)  (into q, reuse)
    ln_kernel<<<MROWS, 256>>>(h, ln2_g, ln2_b, q);
    // ff = gelu(x2 @ w1 + b1)
    tgemm<2><<<gF, 256, SMEM_BYTES>>>(q, w1T, b1, nullptr, ff, MROWS, FF, DD);
    // out = h + ff @ w2 + b2
    tgemm<1><<<gD, 256, SMEM_BYTES>>>(ff, w2T, b2, h, out, MROWS, DD, FF);
}

// round 6
// speedup vs baseline: 1.1109x; 1.1109x over previous
#include <cuda_runtime.h>
#include <cuda_bf16.h>
#include <cstdint>
#include <math.h>

// Problem dims
#define BB   4
#define SS   2048
#define DD   1024
#define HH   16
#define FF   4096
#define MROWS (BB*SS)          // 8192
#define NBLK (SS/64)           // 32

// ---------------- scratch (device globals; no allocation allowed) ----------
__device__ float g_x1[MROWS*DD];   // LN1 output; reused as attention O
__device__ float g_q [MROWS*DD];   // Q; reused as x2 (LN2 output)
__device__ float g_k [MROWS*DD];
__device__ float g_v [MROWS*DD];
__device__ float g_h [MROWS*DD];   // residual stream after attention
__device__ float g_ff[MROWS*FF];   // GELU MLP intermediate
// transposed weights (N-major "Bt[n][k]" for the mma B operand)
__device__ float g_wqT[DD*DD];
__device__ float g_wkT[DD*DD];
__device__ float g_wvT[DD*DD];
__device__ float g_woT[DD*DD];
__device__ float g_w1T[FF*DD];     // [4096][1024]
__device__ float g_w2T[DD*FF];     // [1024][4096]

// ---------------- PTX helpers (base-target-safe only) -----------------------
__device__ __forceinline__ uint32_t smem_u32(const void* p) {
    uint32_t a;
    asm("{ .reg .u64 t; cvta.to.shared.u64 t, %1; cvt.u32.u64 %0, t; }"
        : "=r"(a) : "l"(p));
    return a;
}
__device__ __forceinline__ void cp16(uint32_t dst, const void* src) {
    asm volatile("cp.async.cg.shared.global [%0], [%1], 16;"
                 :: "r"(dst), "l"(src) : "memory");
}
#define CP_COMMIT() asm volatile("cp.async.commit_group;" ::: "memory")
#define CP_WAIT(n)  asm volatile("cp.async.wait_group %0;" :: "n"(n) : "memory")

__device__ __forceinline__ void mma_tf32(float* d, const uint32_t* a,
                                         const uint32_t* b) {
    asm volatile(
        "mma.sync.aligned.m16n8k8.row.col.f32.tf32.tf32.f32 "
        "{%0,%1,%2,%3}, {%4,%5,%6,%7}, {%8,%9}, {%0,%1,%2,%3};"
        : "+f"(d[0]), "+f"(d[1]), "+f"(d[2]), "+f"(d[3])
        : "r"(a[0]), "r"(a[1]), "r"(a[2]), "r"(a[3]), "r"(b[0]), "r"(b[1]));
}
// ldmatrix x4: each 8x8 b16 matrix == 8row x 4col float block; thread t gets
// float[t/4][t%4] -> exactly one tf32 mma fragment slot per matrix.
__device__ __forceinline__ void ldsm_x4(uint32_t* r, uint32_t saddr) {
    asm volatile("ldmatrix.sync.aligned.m8n8.x4.shared.b16 {%0,%1,%2,%3}, [%4];"
        : "=r"(r[0]), "=r"(r[1]), "=r"(r[2]), "=r"(r[3]) : "r"(saddr));
}

// ---------------- LayerNorm (one block per row, D=1024) --------------------
__global__ __launch_bounds__(256) void ln_kernel(
    const float* __restrict__ x, const float* __restrict__ g,
    const float* __restrict__ b, float* __restrict__ y)
{
    __shared__ float rs[8], rq[8];
    int row = blockIdx.x, t = threadIdx.x;
    const float4* xr = reinterpret_cast<const float4*>(x) + (size_t)row * 256;
    float4 v = xr[t];
    float s = v.x + v.y + v.z + v.w;
    float q = fmaf(v.x, v.x, fmaf(v.y, v.y, fmaf(v.z, v.z, v.w * v.w)));
    #pragma unroll
    for (int o = 16; o; o >>= 1) {
        s += __shfl_xor_sync(0xffffffffu, s, o);
        q += __shfl_xor_sync(0xffffffffu, q, o);
    }
    if ((t & 31) == 0) { rs[t >> 5] = s; rq[t >> 5] = q; }
    __syncthreads();
    float ts = 0.f, tq = 0.f;
    #pragma unroll
    for (int i = 0; i < 8; i++) { ts += rs[i]; tq += rq[i]; }
    float mean = ts * (1.0f / 1024.0f);
    float var  = tq * (1.0f / 1024.0f) - mean * mean;
    float inv  = rsqrtf(var + 1e-5f);
    float4 gg = reinterpret_cast<const float4*>(g)[t];
    float4 bb = reinterpret_cast<const float4*>(b)[t];
    float4 o4;
    o4.x = (v.x - mean) * inv * gg.x + bb.x;
    o4.y = (v.y - mean) * inv * gg.y + bb.y;
    o4.z = (v.z - mean) * inv * gg.z + bb.z;
    o4.w = (v.w - mean) * inv * gg.w + bb.w;
    reinterpret_cast<float4*>(y)[(size_t)row * 256 + t] = o4;
}

// ---------------- weight transpose: in[K][N] -> out[N][K] -------------------
__global__ __launch_bounds__(256) void transpose_kernel(
    const float* __restrict__ in, float* __restrict__ out, int K, int N)
{
    __shared__ float t[32][33];
    int tx = threadIdx.x, ty = threadIdx.y;        // 32 x 8
    int bn = blockIdx.x * 32, bk = blockIdx.y * 32;
    #pragma unroll
    for (int i = 0; i < 4; i++)
        t[ty + 8 * i][tx] = in[(size_t)(bk + ty + 8 * i) * N + bn + tx];
    __syncthreads();
    #pragma unroll
    for (int i = 0; i < 4; i++)
        out[(size_t)(bn + ty + 8 * i) * K + bk + tx] = t[tx][ty + 8 * i];
}

// ---------------- tf32 mma.sync GEMM, ldmatrix fragments --------------------
// C[M,N] = A[M,K] @ Bt[N,K]^T + bias, epilogue
// EPI: 0 = bias, 1 = bias + residual, 2 = bias + exact GELU
// CTA tile 128x128, K-chunk 32, STAGES=3, ldmatrix.x4 fragment loads.
#define LDS36 36
#define TILE_F (128 * LDS36)               // 4608 floats per operand tile
#define STAGES 3
#define SMEM_BYTES (STAGES * 2 * TILE_F * 4)   // 110592 bytes

template<int EPI>
__global__ __launch_bounds__(256, 2) void tgemm(
    const float* __restrict__ A, const float* __restrict__ Bt,
    const float* __restrict__ bias, const float* __restrict__ res,
    float* __restrict__ C, int M, int N, int K)
{
    extern __shared__ float smf[];
    const uint32_t sbase = smem_u32(smf);
    const int tid  = threadIdx.x;
    const int wid  = tid >> 5;
    const int lane = tid & 31;
    const int g    = lane >> 2;        // groupID
    const int c    = lane & 3;         // threadID_in_group
    const int warp_m = wid & 3;        // 4 warps down M (32 rows each)
    const int warp_n = wid >> 2;       // 2 warps across N (64 cols each)
    const int bm = blockIdx.y * 128;
    const int bn = blockIdx.x * 128;

    // ldmatrix per-lane source coordinates
    // A: matrices (rows r..r+7 | r+8..r+15) x (cols k0..k0+3 | k0+4..k0+7)
    const uint32_t aoff = (uint32_t)(
        (warp_m * 32 + (lane & 7) + ((lane >> 3) & 1) * 8) * LDS36
        + ((lane >> 4) & 1) * 4) * 4u;
    // B: matrices (rows n0..n0+7: col k0, col k0+4 | rows n0+8..n0+15: ...)
    const uint32_t boff = (uint32_t)(
        (warp_n * 64 + (lane & 7) + ((lane >> 4) & 1) * 8) * LDS36
        + ((lane >> 3) & 1) * 4) * 4u;

    // loader coords: 4 float4 per operand per thread per chunk
    const int r0 = tid >> 3;           // rows r0, r0+32, r0+64, r0+96
    const int u0 = tid & 7;            // 16B slot in the 32-float k-chunk

    const float* aptr = A  + (size_t)(bm + r0) * K + u0 * 4;
    const float* bptr = Bt + (size_t)(bn + r0) * K + u0 * 4;
    const uint32_t soff0 = (uint32_t)(r0 * LDS36 + u0 * 4) * 4u;

    float acc[2][8][4];
    #pragma unroll
    for (int i = 0; i < 2; i++)
        #pragma unroll
        for (int j = 0; j < 8; j++)
            #pragma unroll
            for (int r = 0; r < 4; r++) acc[i][j][r] = 0.f;

    const int NK = K >> 5;

    auto issue = [&](int kc, int s) {
        const uint32_t stA = sbase + (uint32_t)(s * 2) * TILE_F * 4u;
        const uint32_t stB = stA + TILE_F * 4u;
        const float* ap = aptr + (size_t)kc * 32;
        const float* bp = bptr + (size_t)kc * 32;
        #pragma unroll
        for (int t = 0; t < 4; t++) {
            const uint32_t so = soff0 + (uint32_t)(t * 32 * LDS36) * 4u;
            cp16(stA + so, ap + (size_t)(t * 32) * K);
            cp16(stB + so, bp + (size_t)(t * 32) * K);
        }
    };

    issue(0, 0); CP_COMMIT();
    issue(1, 1); CP_COMMIT();

    int s_rd = 0, s_wr = 2;
    for (int k = 0; k < NK; k++) {
        CP_WAIT(1);
        __syncthreads();
        if (k + 2 < NK) issue(k + 2, s_wr);
        CP_COMMIT();
        s_wr = (s_wr == STAGES - 1) ? 0 : s_wr + 1;

        const uint32_t sA = sbase + (uint32_t)(s_rd * 2) * TILE_F * 4u;
        const uint32_t sB = sA + TILE_F * 4u;
        s_rd = (s_rd == STAGES - 1) ? 0 : s_rd + 1;

        #pragma unroll
        for (int ks = 0; ks < 4; ks++) {
            uint32_t afr[2][4], bfr4[4][4];
            ldsm_x4(afr[0], sA + aoff + (uint32_t)ks * 32u);
            ldsm_x4(afr[1], sA + aoff + (uint32_t)(16 * LDS36 * 4) + (uint32_t)ks * 32u);
            #pragma unroll
            for (int p = 0; p < 4; p++)
                ldsm_x4(bfr4[p], sB + boff + (uint32_t)(16 * p * LDS36 * 4) + (uint32_t)ks * 32u);
            #pragma unroll
            for (int im = 0; im < 2; im++)
                #pragma unroll
                for (int p = 0; p < 4; p++) {
                    mma_tf32(acc[im][2 * p],     afr[im], &bfr4[p][0]);
                    mma_tf32(acc[im][2 * p + 1], afr[im], &bfr4[p][2]);
                }
        }
    }

    // ---- epilogue ----
    #pragma unroll
    for (int im = 0; im < 2; im++) {
        #pragma unroll
        for (int half = 0; half < 2; half++) {
            const int row = bm + warp_m * 32 + im * 16 + g + half * 8;
            #pragma unroll
            for (int in = 0; in < 8; in++) {
                const int col = bn + warp_n * 64 + in * 8 + 2 * c;
                float v0 = acc[im][in][half * 2 + 0] + bias[col];
                float v1 = acc[im][in][half * 2 + 1] + bias[col + 1];
                if (EPI == 1) {
                    const float2 rr = *reinterpret_cast<const float2*>(
                        &res[(size_t)row * N + col]);
                    v0 += rr.x; v1 += rr.y;
                }
                if (EPI == 2) {
                    v0 = 0.5f * v0 * (1.0f + erff(v0 * 0.70710678118654752f));
                    v1 = 0.5f * v1 * (1.0f + erff(v1 * 0.70710678118654752f));
                }
                float2 o2 = make_float2(v0, v1);
                *reinterpret_cast<float2*>(&C[(size_t)row * N + col]) = o2;
            }
        }
    }
}

// ---------------- block-sparse attention (one CTA per (b,h,block)) ---------
__global__ __launch_bounds__(256) void attention_kernel(
    const float* __restrict__ Q, const float* __restrict__ K,
    const float* __restrict__ V, float* __restrict__ O,
    float* __restrict__ W)
{
    __shared__ float qs[64][65];
    __shared__ float ks[64][65];
    int tid = threadIdx.x;
    int blk = blockIdx.x;                    // b*512 + h*32 + n
    int n = blk & 31, hh = (blk >> 5) & 15, b = blk >> 9;
    size_t base = ((size_t)(b * SS + n * 64)) * DD + hh * 64;

    for (int i = tid; i < 4096; i += 256) {
        int r = i >> 6, c = i & 63;
        qs[r][c] = Q[base + (size_t)r * DD + c] * 0.125f;  // 1/sqrt(64)
        ks[r][c] = K[base + (size_t)r * DD + c];
    }
    __syncthreads();

    int qi  = tid >> 2;
    int kj0 = (tid & 3) << 4;
    float w[16];
    #pragma unroll
    for (int j = 0; j < 16; j++) {
        float acc = 0.f;
        #pragma unroll
        for (int d = 0; d < 64; d++)
            acc = fmaf(qs[qi][d], ks[kj0 + j][d], acc);
        w[j] = acc;
    }
    float m = w[0];
    #pragma unroll
    for (int j = 1; j < 16; j++) m = fmaxf(m, w[j]);
    m = fmaxf(m, __shfl_xor_sync(0xffffffffu, m, 1));
    m = fmaxf(m, __shfl_xor_sync(0xffffffffu, m, 2));
    float s = 0.f;
    #pragma unroll
    for (int j = 0; j < 16; j++) { w[j] = __expf(w[j] - m); s += w[j]; }
    s += __shfl_xor_sync(0xffffffffu, s, 1);
    s += __shfl_xor_sync(0xffffffffu, s, 2);
    float inv = 1.0f / s;
    #pragma unroll
    for (int j = 0; j < 16; j++) w[j] *= inv;

    if (W) {
        float* wout = W + (size_t)blk * 4096 + qi * 64 + kj0;
        #pragma unroll
        for (int j = 0; j < 16; j++) wout[j] = w[j];
    }

    __syncthreads();
    for (int i = tid; i < 4096; i += 256) {
        int r = i >> 6, c = i & 63;
        qs[r][c] = V[base + (size_t)r * DD + c];
    }
    __syncthreads();

    #pragma unroll
    for (int dc = 0; dc < 4; dc++) {
        float p[16];
        #pragma unroll
        for (int jj = 0; jj < 16; jj++) {
            int d = dc * 16 + jj;
            float acc = 0.f;
            #pragma unroll
            for (int j = 0; j < 16; j++)
                acc = fmaf(w[j], qs[kj0 + j][d], acc);
            p[jj] = acc;
        }
        #pragma unroll
        for (int jj = 0; jj < 16; jj++) {
            p[jj] += __shfl_xor_sync(0xffffffffu, p[jj], 1);
            p[jj] += __shfl_xor_sync(0xffffffffu, p[jj], 2);
        }
        if ((tid & 3) == dc) {
            #pragma unroll
            for (int jj = 0; jj < 16; jj++)
                O[base + (size_t)qi * DD + dc * 16 + jj] = p[jj];
        }
    }
}

// ---------------- host launcher ---------------------------------------------
extern "C" void kernel_launch(void* const* d_in, const int* in_sizes, int n_in,
                              void* d_out, int out_size)
{
    const float* hidden = (const float*)d_in[0];
    const float* ln1_g  = (const float*)d_in[1];
    const float* ln1_b  = (const float*)d_in[2];
    const float* ln2_g  = (const float*)d_in[3];
    const float* ln2_b  = (const float*)d_in[4];
    const float* wq = (const float*)d_in[5];  const float* bq = (const float*)d_in[6];
    const float* wk = (const float*)d_in[7];  const float* bk = (const float*)d_in[8];
    const float* wv = (const float*)d_in[9];  const float* bv = (const float*)d_in[10];
    const float* wo = (const float*)d_in[11]; const float* bo = (const float*)d_in[12];
    const float* w1 = (const float*)d_in[13]; const float* b1 = (const float*)d_in[14];
    const float* w2 = (const float*)d_in[15]; const float* b2 = (const float*)d_in[16];
    float* out = (float*)d_out;

    float *x1, *q, *k, *v, *h, *ff;
    float *wqT, *wkT, *wvT, *woT, *w1T, *w2T;
    cudaGetSymbolAddress((void**)&x1, g_x1);
    cudaGetSymbolAddress((void**)&q,  g_q);
    cudaGetSymbolAddress((void**)&k,  g_k);
    cudaGetSymbolAddress((void**)&v,  g_v);
    cudaGetSymbolAddress((void**)&h,  g_h);
    cudaGetSymbolAddress((void**)&ff, g_ff);
    cudaGetSymbolAddress((void**)&wqT, g_wqT);
    cudaGetSymbolAddress((void**)&wkT, g_wkT);
    cudaGetSymbolAddress((void**)&wvT, g_wvT);
    cudaGetSymbolAddress((void**)&woT, g_woT);
    cudaGetSymbolAddress((void**)&w1T, g_w1T);
    cudaGetSymbolAddress((void**)&w2T, g_w2T);

    cudaFuncSetAttribute(tgemm<0>, cudaFuncAttributeMaxDynamicSharedMemorySize, SMEM_BYTES);
    cudaFuncSetAttribute(tgemm<1>, cudaFuncAttributeMaxDynamicSharedMemorySize, SMEM_BYTES);
    cudaFuncSetAttribute(tgemm<2>, cudaFuncAttributeMaxDynamicSharedMemorySize, SMEM_BYTES);

    const int MAIN_ELEMS = MROWS * DD;                 // 8388608
    const int ATTW_ELEMS = BB * HH * NBLK * 64 * 64;   // 8388608
    float* attw = (out_size >= MAIN_ELEMS + ATTW_ELEMS) ? out + MAIN_ELEMS
                                                        : nullptr;

    dim3 tb(32, 8);
    transpose_kernel<<<dim3(DD/32, DD/32), tb>>>(wq, wqT, DD, DD);
    transpose_kernel<<<dim3(DD/32, DD/32), tb>>>(wk, wkT, DD, DD);
    transpose_kernel<<<dim3(DD/32, DD/32), tb>>>(wv, wvT, DD, DD);
    transpose_kernel<<<dim3(DD/32, DD/32), tb>>>(wo, woT, DD, DD);
    transpose_kernel<<<dim3(FF/32, DD/32), tb>>>(w1, w1T, DD, FF);
    transpose_kernel<<<dim3(DD/32, FF/32), tb>>>(w2, w2T, FF, DD);

    dim3 gD(DD / 128, MROWS / 128);   // (8, 64)
    dim3 gF(FF / 128, MROWS / 128);   // (32, 64)

    // x1 = LN1(hidden)
    ln_kernel<<<MROWS, 256>>>(hidden, ln1_g, ln1_b, x1);
    // q/k/v = x1 @ w{q,k,v} + b
    tgemm<0><<<gD, 256, SMEM_BYTES>>>(x1, wqT, bq, nullptr, q, MROWS, DD, DD);
    tgemm<0><<<gD, 256, SMEM_BYTES>>>(x1, wkT, bk, nullptr, k, MROWS, DD, DD);
    tgemm<0><<<gD, 256, SMEM_BYTES>>>(x1, wvT, bv, nullptr, v, MROWS, DD, DD);
    // block attention: O into x1; optional attn_w out
    attention_kernel<<<BB * HH * NBLK, 256>>>(q, k, v, x1, attw);
    // h = hidden + O @ wo + bo
    tgemm<1><<<gD, 256, SMEM_BYTES>>>(x1, woT, bo, hidden, h, MROWS, DD, DD);
    // x2 = LN2(h)  (into q, reuse)
    ln_kernel<<<MROWS, 256>>>(h, ln2_g, ln2_b, q);
    // ff = gelu(x2 @ w1 + b1)
    tgemm<2><<<gF, 256, SMEM_BYTES>>>(q, w1T, b1, nullptr, ff, MROWS, FF, DD);
    // out = h + ff @ w2 + b2
    tgemm<1><<<gD, 256, SMEM_BYTES>>>(ff, w2T, b2, h, out, MROWS, DD, FF);
}

// round 7
// speedup vs baseline: 1.1452x; 1.0308x over previous
#include <cuda_runtime.h>
#include <cuda_bf16.h>
#include <cstdint>
#include <math.h>

// Problem dims
#define BB   4
#define SS   2048
#define DD   1024
#define HH   16
#define FF   4096
#define MROWS (BB*SS)          // 8192
#define NBLK (SS/64)           // 32

// ---------------- scratch (device globals; no allocation allowed) ----------
__device__ float g_x1[MROWS*DD];   // LN1 output; reused as attention O
__device__ float g_q [MROWS*DD];   // Q; reused as x2 (LN2 output)
__device__ float g_k [MROWS*DD];
__device__ float g_v [MROWS*DD];
__device__ float g_h [MROWS*DD];   // residual stream after attention
__device__ float g_ff[MROWS*FF];   // GELU MLP intermediate
// transposed weights (N-major "Bt[n][k]" for the mma B operand)
__device__ float g_wqT[DD*DD];
__device__ float g_wkT[DD*DD];
__device__ float g_wvT[DD*DD];
__device__ float g_woT[DD*DD];
__device__ float g_w1T[FF*DD];     // [4096][1024]
__device__ float g_w2T[DD*FF];     // [1024][4096]

// ---------------- PTX helpers (base-target-safe only) -----------------------
__device__ __forceinline__ uint32_t smem_u32(const void* p) {
    uint32_t a;
    asm("{ .reg .u64 t; cvta.to.shared.u64 t, %1; cvt.u32.u64 %0, t; }"
        : "=r"(a) : "l"(p));
    return a;
}
__device__ __forceinline__ void cp16(uint32_t dst, const void* src) {
    asm volatile("cp.async.cg.shared.global [%0], [%1], 16;"
                 :: "r"(dst), "l"(src) : "memory");
}
#define CP_COMMIT() asm volatile("cp.async.commit_group;" ::: "memory")
#define CP_WAIT(n)  asm volatile("cp.async.wait_group %0;" :: "n"(n) : "memory")

// NOTE: non-volatile on purpose — pure register semantics; lets ptxas
// software-pipeline MMAs into LDSM latency shadows.
__device__ __forceinline__ void mma_tf32(float* d, const uint32_t* a,
                                         const uint32_t* b) {
    asm("mma.sync.aligned.m16n8k8.row.col.f32.tf32.tf32.f32 "
        "{%0,%1,%2,%3}, {%4,%5,%6,%7}, {%8,%9}, {%0,%1,%2,%3};"
        : "+f"(d[0]), "+f"(d[1]), "+f"(d[2]), "+f"(d[3])
        : "r"(a[0]), "r"(a[1]), "r"(a[2]), "r"(a[3]), "r"(b[0]), "r"(b[1]));
}
// ldmatrix x4: each 8x8 b16 matrix == 8row x 4col float block; thread t gets
// float[t/4][t%4] -> exactly one tf32 mma fragment slot per matrix.
// Stays volatile: must not move across __syncthreads / cp.async stores.
__device__ __forceinline__ void ldsm_x4(uint32_t* r, uint32_t saddr) {
    asm volatile("ldmatrix.sync.aligned.m8n8.x4.shared.b16 {%0,%1,%2,%3}, [%4];"
        : "=r"(r[0]), "=r"(r[1]), "=r"(r[2]), "=r"(r[3]) : "r"(saddr));
}

// ---------------- LayerNorm (one block per row, D=1024) --------------------
__global__ __launch_bounds__(256) void ln_kernel(
    const float* __restrict__ x, const float* __restrict__ g,
    const float* __restrict__ b, float* __restrict__ y)
{
    __shared__ float rs[8], rq[8];
    int row = blockIdx.x, t = threadIdx.x;
    const float4* xr = reinterpret_cast<const float4*>(x) + (size_t)row * 256;
    float4 v = xr[t];
    float s = v.x + v.y + v.z + v.w;
    float q = fmaf(v.x, v.x, fmaf(v.y, v.y, fmaf(v.z, v.z, v.w * v.w)));
    #pragma unroll
    for (int o = 16; o; o >>= 1) {
        s += __shfl_xor_sync(0xffffffffu, s, o);
        q += __shfl_xor_sync(0xffffffffu, q, o);
    }
    if ((t & 31) == 0) { rs[t >> 5] = s; rq[t >> 5] = q; }
    __syncthreads();
    float ts = 0.f, tq = 0.f;
    #pragma unroll
    for (int i = 0; i < 8; i++) { ts += rs[i]; tq += rq[i]; }
    float mean = ts * (1.0f / 1024.0f);
    float var  = tq * (1.0f / 1024.0f) - mean * mean;
    float inv  = rsqrtf(var + 1e-5f);
    float4 gg = reinterpret_cast<const float4*>(g)[t];
    float4 bb = reinterpret_cast<const float4*>(b)[t];
    float4 o4;
    o4.x = (v.x - mean) * inv * gg.x + bb.x;
    o4.y = (v.y - mean) * inv * gg.y + bb.y;
    o4.z = (v.z - mean) * inv * gg.z + bb.z;
    o4.w = (v.w - mean) * inv * gg.w + bb.w;
    reinterpret_cast<float4*>(y)[(size_t)row * 256 + t] = o4;
}

// ---------------- batched weight transposes ---------------------------------
// Shared tile body: transpose in[K][N] -> out[N][K], one 32x32 tile.
__device__ __forceinline__ void transpose_tile(
    const float* __restrict__ in, float* __restrict__ out,
    int K, int N, int bk, int bn, int tx, int ty)
{
    __shared__ float t[32][33];
    #pragma unroll
    for (int i = 0; i < 4; i++)
        t[ty + 8 * i][tx] = in[(size_t)(bk + ty + 8 * i) * N + bn + tx];
    __syncthreads();
    #pragma unroll
    for (int i = 0; i < 4; i++)
        out[(size_t)(bn + ty + 8 * i) * K + bk + tx] = t[tx][ty + 8 * i];
}

// QKV weights: three 1024x1024 transposes in one launch (grid.x = 3072)
__global__ __launch_bounds__(256) void transposeA_kernel(
    const float* __restrict__ wq, const float* __restrict__ wk,
    const float* __restrict__ wv,
    float* __restrict__ wqT, float* __restrict__ wkT, float* __restrict__ wvT)
{
    int b = blockIdx.x;
    int job = b >> 10, t = b & 1023;
    const float* in = (job == 0) ? wq : (job == 1) ? wk : wv;
    float* out      = (job == 0) ? wqT : (job == 1) ? wkT : wvT;
    int bn = (t & 31) * 32, bk = (t >> 5) * 32;
    transpose_tile(in, out, DD, DD, bk, bn, threadIdx.x, threadIdx.y);
}

// wo (1024x1024), w1 (1024x4096), w2 (4096x1024) in one launch (grid = 9216)
__global__ __launch_bounds__(256) void transposeB_kernel(
    const float* __restrict__ wo, const float* __restrict__ w1,
    const float* __restrict__ w2,
    float* __restrict__ woT, float* __restrict__ w1T, float* __restrict__ w2T)
{
    int b = blockIdx.x;
    const float* in; float* out; int K, N, t;
    if (b < 1024)      { in = wo; out = woT; K = DD; N = DD; t = b; }
    else if (b < 5120) { in = w1; out = w1T; K = DD; N = FF; t = b - 1024; }
    else               { in = w2; out = w2T; K = FF; N = DD; t = b - 5120; }
    int ntx = N / 32;
    int bn = (t % ntx) * 32, bk = (t / ntx) * 32;
    transpose_tile(in, out, K, N, bk, bn, threadIdx.x, threadIdx.y);
}

// ---------------- tf32 mma.sync GEMM core (ldmatrix fragments) --------------
// C[M,N] = A[M,K] @ Bt[N,K]^T + bias, epilogue
// EPI: 0 = bias, 1 = bias + residual, 2 = bias + exact GELU
// CTA tile 128x128, K-chunk 32, STAGES=3.
#define LDS36 36
#define TILE_F (128 * LDS36)               // 4608 floats per operand tile
#define STAGES 3
#define SMEM_BYTES (STAGES * 2 * TILE_F * 4)   // 110592 bytes

template<int EPI>
__device__ __forceinline__ void tgemm_core(
    const float* __restrict__ A, const float* __restrict__ Bt,
    const float* __restrict__ bias, const float* __restrict__ res,
    float* __restrict__ C, int M, int N, int K, int bm, int bn)
{
    extern __shared__ float smf[];
    const uint32_t sbase = smem_u32(smf);
    const int tid  = threadIdx.x;
    const int wid  = tid >> 5;
    const int lane = tid & 31;
    const int g    = lane >> 2;        // groupID
    const int c    = lane & 3;         // threadID_in_group
    const int warp_m = wid & 3;        // 4 warps down M (32 rows each)
    const int warp_n = wid >> 2;       // 2 warps across N (64 cols each)

    // ldmatrix per-lane source coordinates
    const uint32_t aoff = (uint32_t)(
        (warp_m * 32 + (lane & 7) + ((lane >> 3) & 1) * 8) * LDS36
        + ((lane >> 4) & 1) * 4) * 4u;
    const uint32_t boff = (uint32_t)(
        (warp_n * 64 + (lane & 7) + ((lane >> 4) & 1) * 8) * LDS36
        + ((lane >> 3) & 1) * 4) * 4u;

    // loader coords: 4 float4 per operand per thread per chunk
    const int r0 = tid >> 3;
    const int u0 = tid & 7;

    const float* aptr = A  + (size_t)(bm + r0) * K + u0 * 4;
    const float* bptr = Bt + (size_t)(bn + r0) * K + u0 * 4;
    const uint32_t soff0 = (uint32_t)(r0 * LDS36 + u0 * 4) * 4u;

    float acc[2][8][4];
    #pragma unroll
    for (int i = 0; i < 2; i++)
        #pragma unroll
        for (int j = 0; j < 8; j++)
            #pragma unroll
            for (int r = 0; r < 4; r++) acc[i][j][r] = 0.f;

    const int NK = K >> 5;

    auto issue = [&](int kc, int s) {
        const uint32_t stA = sbase + (uint32_t)(s * 2) * TILE_F * 4u;
        const uint32_t stB = stA + TILE_F * 4u;
        const float* ap = aptr + (size_t)kc * 32;
        const float* bp = bptr + (size_t)kc * 32;
        #pragma unroll
        for (int t = 0; t < 4; t++) {
            const uint32_t so = soff0 + (uint32_t)(t * 32 * LDS36) * 4u;
            cp16(stA + so, ap + (size_t)(t * 32) * K);
            cp16(stB + so, bp + (size_t)(t * 32) * K);
        }
    };

    issue(0, 0); CP_COMMIT();
    issue(1, 1); CP_COMMIT();

    int s_rd = 0, s_wr = 2;
    for (int k = 0; k < NK; k++) {
        CP_WAIT(1);
        __syncthreads();
        if (k + 2 < NK) issue(k + 2, s_wr);
        CP_COMMIT();
        s_wr = (s_wr == STAGES - 1) ? 0 : s_wr + 1;

        const uint32_t sA = sbase + (uint32_t)(s_rd * 2) * TILE_F * 4u;
        const uint32_t sB = sA + TILE_F * 4u;
        s_rd = (s_rd == STAGES - 1) ? 0 : s_rd + 1;

        #pragma unroll
        for (int ks = 0; ks < 4; ks++) {
            uint32_t afr[2][4], bfr4[4][4];
            ldsm_x4(afr[0], sA + aoff + (uint32_t)ks * 32u);
            ldsm_x4(afr[1], sA + aoff + (uint32_t)(16 * LDS36 * 4) + (uint32_t)ks * 32u);
            #pragma unroll
            for (int p = 0; p < 4; p++)
                ldsm_x4(bfr4[p], sB + boff + (uint32_t)(16 * p * LDS36 * 4) + (uint32_t)ks * 32u);
            #pragma unroll
            for (int im = 0; im < 2; im++)
                #pragma unroll
                for (int p = 0; p < 4; p++) {
                    mma_tf32(acc[im][2 * p],     afr[im], &bfr4[p][0]);
                    mma_tf32(acc[im][2 * p + 1], afr[im], &bfr4[p][2]);
                }
        }
    }

    // ---- epilogue ----
    #pragma unroll
    for (int im = 0; im < 2; im++) {
        #pragma unroll
        for (int half = 0; half < 2; half++) {
            const int row = bm + warp_m * 32 + im * 16 + g + half * 8;
            #pragma unroll
            for (int in = 0; in < 8; in++) {
                const int col = bn + warp_n * 64 + in * 8 + 2 * c;
                float v0 = acc[im][in][half * 2 + 0] + bias[col];
                float v1 = acc[im][in][half * 2 + 1] + bias[col + 1];
                if (EPI == 1) {
                    const float2 rr = *reinterpret_cast<const float2*>(
                        &res[(size_t)row * N + col]);
                    v0 += rr.x; v1 += rr.y;
                }
                if (EPI == 2) {
                    v0 = 0.5f * v0 * (1.0f + erff(v0 * 0.70710678118654752f));
                    v1 = 0.5f * v1 * (1.0f + erff(v1 * 0.70710678118654752f));
                }
                float2 o2 = make_float2(v0, v1);
                *reinterpret_cast<float2*>(&C[(size_t)row * N + col]) = o2;
            }
        }
    }
}

template<int EPI>
__global__ __launch_bounds__(256, 2) void tgemm(
    const float* __restrict__ A, const float* __restrict__ Bt,
    const float* __restrict__ bias, const float* __restrict__ res,
    float* __restrict__ C, int M, int N, int K)
{
    tgemm_core<EPI>(A, Bt, bias, res, C, M, N, K,
                    blockIdx.y * 128, blockIdx.x * 128);
}

// fused QKV: grid.z selects weight/bias/output; same A for all three
__global__ __launch_bounds__(256, 2) void tgemm_qkv(
    const float* __restrict__ A,
    const float* __restrict__ wqT, const float* __restrict__ wkT,
    const float* __restrict__ wvT,
    const float* __restrict__ bq, const float* __restrict__ bk,
    const float* __restrict__ bv,
    float* __restrict__ Q, float* __restrict__ Ko, float* __restrict__ V)
{
    const int z = blockIdx.z;
    const float* Bt   = (z == 0) ? wqT : (z == 1) ? wkT : wvT;
    const float* bias = (z == 0) ? bq  : (z == 1) ? bk  : bv;
    float* C          = (z == 0) ? Q   : (z == 1) ? Ko  : V;
    tgemm_core<0>(A, Bt, bias, nullptr, C, MROWS, DD, DD,
                  blockIdx.y * 128, blockIdx.x * 128);
}

// ---------------- block-sparse attention (one CTA per (b,h,block)) ---------
__global__ __launch_bounds__(256) void attention_kernel(
    const float* __restrict__ Q, const float* __restrict__ K,
    const float* __restrict__ V, float* __restrict__ O,
    float* __restrict__ W)
{
    __shared__ float qs[64][65];
    __shared__ float ks[64][65];
    int tid = threadIdx.x;
    int blk = blockIdx.x;                    // b*512 + h*32 + n
    int n = blk & 31, hh = (blk >> 5) & 15, b = blk >> 9;
    size_t base = ((size_t)(b * SS + n * 64)) * DD + hh * 64;

    for (int i = tid; i < 4096; i += 256) {
        int r = i >> 6, c = i & 63;
        qs[r][c] = Q[base + (size_t)r * DD + c] * 0.125f;  // 1/sqrt(64)
        ks[r][c] = K[base + (size_t)r * DD + c];
    }
    __syncthreads();

    int qi  = tid >> 2;
    int kj0 = (tid & 3) << 4;
    float w[16];
    #pragma unroll
    for (int j = 0; j < 16; j++) {
        float acc = 0.f;
        #pragma unroll
        for (int d = 0; d < 64; d++)
            acc = fmaf(qs[qi][d], ks[kj0 + j][d], acc);
        w[j] = acc;
    }
    float m = w[0];
    #pragma unroll
    for (int j = 1; j < 16; j++) m = fmaxf(m, w[j]);
    m = fmaxf(m, __shfl_xor_sync(0xffffffffu, m, 1));
    m = fmaxf(m, __shfl_xor_sync(0xffffffffu, m, 2));
    float s = 0.f;
    #pragma unroll
    for (int j = 0; j < 16; j++) { w[j] = __expf(w[j] - m); s += w[j]; }
    s += __shfl_xor_sync(0xffffffffu, s, 1);
    s += __shfl_xor_sync(0xffffffffu, s, 2);
    float inv = 1.0f / s;
    #pragma unroll
    for (int j = 0; j < 16; j++) w[j] *= inv;

    if (W) {
        float* wout = W + (size_t)blk * 4096 + qi * 64 + kj0;
        #pragma unroll
        for (int j = 0; j < 16; j++) wout[j] = w[j];
    }

    __syncthreads();
    for (int i = tid; i < 4096; i += 256) {
        int r = i >> 6, c = i & 63;
        qs[r][c] = V[base + (size_t)r * DD + c];
    }
    __syncthreads();

    #pragma unroll
    for (int dc = 0; dc < 4; dc++) {
        float p[16];
        #pragma unroll
        for (int jj = 0; jj < 16; jj++) {
            int d = dc * 16 + jj;
            float acc = 0.f;
            #pragma unroll
            for (int j = 0; j < 16; j++)
                acc = fmaf(w[j], qs[kj0 + j][d], acc);
            p[jj] = acc;
        }
        #pragma unroll
        for (int jj = 0; jj < 16; jj++) {
            p[jj] += __shfl_xor_sync(0xffffffffu, p[jj], 1);
            p[jj] += __shfl_xor_sync(0xffffffffu, p[jj], 2);
        }
        if ((tid & 3) == dc) {
            #pragma unroll
            for (int jj = 0; jj < 16; jj++)
                O[base + (size_t)qi * DD + dc * 16 + jj] = p[jj];
        }
    }
}

// ---------------- host launcher ---------------------------------------------
extern "C" void kernel_launch(void* const* d_in, const int* in_sizes, int n_in,
                              void* d_out, int out_size)
{
    const float* hidden = (const float*)d_in[0];
    const float* ln1_g  = (const float*)d_in[1];
    const float* ln1_b  = (const float*)d_in[2];
    const float* ln2_g  = (const float*)d_in[3];
    const float* ln2_b  = (const float*)d_in[4];
    const float* wq = (const float*)d_in[5];  const float* bq = (const float*)d_in[6];
    const float* wk = (const float*)d_in[7];  const float* bk = (const float*)d_in[8];
    const float* wv = (const float*)d_in[9];  const float* bv = (const float*)d_in[10];
    const float* wo = (const float*)d_in[11]; const float* bo = (const float*)d_in[12];
    const float* w1 = (const float*)d_in[13]; const float* b1 = (const float*)d_in[14];
    const float* w2 = (const float*)d_in[15]; const float* b2 = (const float*)d_in[16];
    float* out = (float*)d_out;

    float *x1, *q, *k, *v, *h, *ff;
    float *wqT, *wkT, *wvT, *woT, *w1T, *w2T;
    cudaGetSymbolAddress((void**)&x1, g_x1);
    cudaGetSymbolAddress((void**)&q,  g_q);
    cudaGetSymbolAddress((void**)&k,  g_k);
    cudaGetSymbolAddress((void**)&v,  g_v);
    cudaGetSymbolAddress((void**)&h,  g_h);
    cudaGetSymbolAddress((void**)&ff, g_ff);
    cudaGetSymbolAddress((void**)&wqT, g_wqT);
    cudaGetSymbolAddress((void**)&wkT, g_wkT);
    cudaGetSymbolAddress((void**)&wvT, g_wvT);
    cudaGetSymbolAddress((void**)&woT, g_woT);
    cudaGetSymbolAddress((void**)&w1T, g_w1T);
    cudaGetSymbolAddress((void**)&w2T, g_w2T);

    cudaFuncSetAttribute(tgemm<0>, cudaFuncAttributeMaxDynamicSharedMemorySize, SMEM_BYTES);
    cudaFuncSetAttribute(tgemm<1>, cudaFuncAttributeMaxDynamicSharedMemorySize, SMEM_BYTES);
    cudaFuncSetAttribute(tgemm<2>, cudaFuncAttributeMaxDynamicSharedMemorySize, SMEM_BYTES);
    cudaFuncSetAttribute(tgemm_qkv, cudaFuncAttributeMaxDynamicSharedMemorySize, SMEM_BYTES);

    const int MAIN_ELEMS = MROWS * DD;                 // 8388608
    const int ATTW_ELEMS = BB * HH * NBLK * 64 * 64;   // 8388608
    float* attw = (out_size >= MAIN_ELEMS + ATTW_ELEMS) ? out + MAIN_ELEMS
                                                        : nullptr;

    dim3 tb(32, 8);
    dim3 gD(DD / 128, MROWS / 128);          // (8, 64)
    dim3 gQKV(DD / 128, MROWS / 128, 3);     // (8, 64, 3)
    dim3 gF(FF / 128, MROWS / 128);          // (32, 64)

    // launch order arranged so ncu (-s 5 -c 1) profiles launch #5 = tgemm<1> (WO)
    // 0: x1 = LN1(hidden)
    ln_kernel<<<MROWS, 256>>>(hidden, ln1_g, ln1_b, x1);
    // 1: transpose QKV weights
    transposeA_kernel<<<3072, tb>>>(wq, wk, wv, wqT, wkT, wvT);
    // 2: q/k/v = x1 @ w{q,k,v} + b (fused, grid.z)
    tgemm_qkv<<<gQKV, 256, SMEM_BYTES>>>(x1, wqT, wkT, wvT, bq, bk, bv, q, k, v);
    // 3: block attention: O into x1; optional attn_w out
    attention_kernel<<<BB * HH * NBLK, 256>>>(q, k, v, x1, attw);
    // 4: transpose wo/w1/w2
    transposeB_kernel<<<9216, tb>>>(wo, w1, w2, woT, w1T, w2T);
    // 5: h = hidden + O @ wo + bo            <-- profiled launch
    tgemm<1><<<gD, 256, SMEM_BYTES>>>(x1, woT, bo, hidden, h, MROWS, DD, DD);
    // 6: x2 = LN2(h)  (into q, reuse)
    ln_kernel<<<MROWS, 256>>>(h, ln2_g, ln2_b, q);
    // 7: ff = gelu(x2 @ w1 + b1)
    tgemm<2><<<gF, 256, SMEM_BYTES>>>(q, w1T, b1, nullptr, ff, MROWS, FF, DD);
    // 8: out = h + ff @ w2 + b2
    tgemm<1><<<gD, 256, SMEM_BYTES>>>(ff, w2T, b2, h, out, MROWS, DD, FF);
}

// round 8
// speedup vs baseline: 1.3685x; 1.1950x over previous
#include <cuda_runtime.h>
#include <cuda_bf16.h>
#include <cstdint>
#include <math.h>

// Problem dims
#define BB   4
#define SS   2048
#define DD   1024
#define HH   16
#define FF   4096
#define MROWS (BB*SS)          // 8192
#define NBLK (SS/64)           // 32

// ---------------- scratch (device globals; no allocation allowed) ----------
__device__ float g_x1[MROWS*DD];   // LN1 output; reused as attention O
__device__ float g_q [MROWS*DD];   // Q; reused as x2 (LN2 output)
__device__ float g_k [MROWS*DD];
__device__ float g_v [MROWS*DD];
__device__ float g_h [MROWS*DD];   // residual stream after attention
__device__ float g_ff[MROWS*FF];   // GELU MLP intermediate
// transposed weights (N-major "Bt[n][k]" for the mma B operand)
__device__ float g_wqT[DD*DD];
__device__ float g_wkT[DD*DD];
__device__ float g_wvT[DD*DD];
__device__ float g_woT[DD*DD];
__device__ float g_w1T[FF*DD];     // [4096][1024]
__device__ float g_w2T[DD*FF];     // [1024][4096]

// ---------------- PTX helpers (base-target-safe only) -----------------------
__device__ __forceinline__ uint32_t smem_u32(const void* p) {
    uint32_t a;
    asm("{ .reg .u64 t; cvta.to.shared.u64 t, %1; cvt.u32.u64 %0, t; }"
        : "=r"(a) : "l"(p));
    return a;
}
__device__ __forceinline__ void cp16(uint32_t dst, const void* src) {
    asm volatile("cp.async.cg.shared.global [%0], [%1], 16;"
                 :: "r"(dst), "l"(src) : "memory");
}
#define CP_COMMIT() asm volatile("cp.async.commit_group;" ::: "memory")
#define CP_WAIT(n)  asm volatile("cp.async.wait_group %0;" :: "n"(n) : "memory")

// NOTE: non-volatile on purpose — pure register semantics; lets ptxas
// software-pipeline MMAs into LDSM latency shadows.
__device__ __forceinline__ void mma_tf32(float* d, const uint32_t* a,
                                         const uint32_t* b) {
    asm("mma.sync.aligned.m16n8k8.row.col.f32.tf32.tf32.f32 "
        "{%0,%1,%2,%3}, {%4,%5,%6,%7}, {%8,%9}, {%0,%1,%2,%3};"
        : "+f"(d[0]), "+f"(d[1]), "+f"(d[2]), "+f"(d[3])
        : "r"(a[0]), "r"(a[1]), "r"(a[2]), "r"(a[3]), "r"(b[0]), "r"(b[1]));
}
// ldmatrix x4: each 8x8 b16 matrix == 8row x 4col float block; thread t gets
// float[t/4][t%4] -> exactly one tf32 mma fragment slot per matrix.
// Stays volatile: must not move across __syncthreads / cp.async stores.
__device__ __forceinline__ void ldsm_x4(uint32_t* r, uint32_t saddr) {
    asm volatile("ldmatrix.sync.aligned.m8n8.x4.shared.b16 {%0,%1,%2,%3}, [%4];"
        : "=r"(r[0]), "=r"(r[1]), "=r"(r[2]), "=r"(r[3]) : "r"(saddr));
}

// ---------------- LayerNorm (one block per row, D=1024) --------------------
__global__ __launch_bounds__(256) void ln_kernel(
    const float* __restrict__ x, const float* __restrict__ g,
    const float* __restrict__ b, float* __restrict__ y)
{
    __shared__ float rs[8], rq[8];
    int row = blockIdx.x, t = threadIdx.x;
    const float4* xr = reinterpret_cast<const float4*>(x) + (size_t)row * 256;
    float4 v = xr[t];
    float s = v.x + v.y + v.z + v.w;
    float q = fmaf(v.x, v.x, fmaf(v.y, v.y, fmaf(v.z, v.z, v.w * v.w)));
    #pragma unroll
    for (int o = 16; o; o >>= 1) {
        s += __shfl_xor_sync(0xffffffffu, s, o);
        q += __shfl_xor_sync(0xffffffffu, q, o);
    }
    if ((t & 31) == 0) { rs[t >> 5] = s; rq[t >> 5] = q; }
    __syncthreads();
    float ts = 0.f, tq = 0.f;
    #pragma unroll
    for (int i = 0; i < 8; i++) { ts += rs[i]; tq += rq[i]; }
    float mean = ts * (1.0f / 1024.0f);
    float var  = tq * (1.0f / 1024.0f) - mean * mean;
    float inv  = rsqrtf(var + 1e-5f);
    float4 gg = reinterpret_cast<const float4*>(g)[t];
    float4 bb = reinterpret_cast<const float4*>(b)[t];
    float4 o4;
    o4.x = (v.x - mean) * inv * gg.x + bb.x;
    o4.y = (v.y - mean) * inv * gg.y + bb.y;
    o4.z = (v.z - mean) * inv * gg.z + bb.z;
    o4.w = (v.w - mean) * inv * gg.w + bb.w;
    reinterpret_cast<float4*>(y)[(size_t)row * 256 + t] = o4;
}

// ---------------- batched weight transposes ---------------------------------
__device__ __forceinline__ void transpose_tile(
    const float* __restrict__ in, float* __restrict__ out,
    int K, int N, int bk, int bn, int tx, int ty)
{
    __shared__ float t[32][33];
    #pragma unroll
    for (int i = 0; i < 4; i++)
        t[ty + 8 * i][tx] = in[(size_t)(bk + ty + 8 * i) * N + bn + tx];
    __syncthreads();
    #pragma unroll
    for (int i = 0; i < 4; i++)
        out[(size_t)(bn + ty + 8 * i) * K + bk + tx] = t[tx][ty + 8 * i];
}

__global__ __launch_bounds__(256) void transposeA_kernel(
    const float* __restrict__ wq, const float* __restrict__ wk,
    const float* __restrict__ wv,
    float* __restrict__ wqT, float* __restrict__ wkT, float* __restrict__ wvT)
{
    int b = blockIdx.x;
    int job = b >> 10, t = b & 1023;
    const float* in = (job == 0) ? wq : (job == 1) ? wk : wv;
    float* out      = (job == 0) ? wqT : (job == 1) ? wkT : wvT;
    int bn = (t & 31) * 32, bk = (t >> 5) * 32;
    transpose_tile(in, out, DD, DD, bk, bn, threadIdx.x, threadIdx.y);
}

__global__ __launch_bounds__(256) void transposeB_kernel(
    const float* __restrict__ wo, const float* __restrict__ w1,
    const float* __restrict__ w2,
    float* __restrict__ woT, float* __restrict__ w1T, float* __restrict__ w2T)
{
    int b = blockIdx.x;
    const float* in; float* out; int K, N, t;
    if (b < 1024)      { in = wo; out = woT; K = DD; N = DD; t = b; }
    else if (b < 5120) { in = w1; out = w1T; K = DD; N = FF; t = b - 1024; }
    else               { in = w2; out = w2T; K = FF; N = DD; t = b - 5120; }
    int ntx = N / 32;
    int bn = (t % ntx) * 32, bk = (t / ntx) * 32;
    transpose_tile(in, out, K, N, bk, bn, threadIdx.x, threadIdx.y);
}

// ---------------- tf32 mma.sync GEMM core (ldmatrix fragments) --------------
#define LDS36 36
#define TILE_F (128 * LDS36)               // 4608 floats per operand tile
#define STAGES 3
#define SMEM_BYTES (STAGES * 2 * TILE_F * 4)   // 110592 bytes

template<int EPI>
__device__ __forceinline__ void tgemm_core(
    const float* __restrict__ A, const float* __restrict__ Bt,
    const float* __restrict__ bias, const float* __restrict__ res,
    float* __restrict__ C, int M, int N, int K, int bm, int bn)
{
    extern __shared__ float smf[];
    const uint32_t sbase = smem_u32(smf);
    const int tid  = threadIdx.x;
    const int wid  = tid >> 5;
    const int lane = tid & 31;
    const int g    = lane >> 2;
    const int c    = lane & 3;
    const int warp_m = wid & 3;
    const int warp_n = wid >> 2;

    const uint32_t aoff = (uint32_t)(
        (warp_m * 32 + (lane & 7) + ((lane >> 3) & 1) * 8) * LDS36
        + ((lane >> 4) & 1) * 4) * 4u;
    const uint32_t boff = (uint32_t)(
        (warp_n * 64 + (lane & 7) + ((lane >> 4) & 1) * 8) * LDS36
        + ((lane >> 3) & 1) * 4) * 4u;

    const int r0 = tid >> 3;
    const int u0 = tid & 7;

    const float* aptr = A  + (size_t)(bm + r0) * K + u0 * 4;
    const float* bptr = Bt + (size_t)(bn + r0) * K + u0 * 4;
    const uint32_t soff0 = (uint32_t)(r0 * LDS36 + u0 * 4) * 4u;

    float acc[2][8][4];
    #pragma unroll
    for (int i = 0; i < 2; i++)
        #pragma unroll
        for (int j = 0; j < 8; j++)
            #pragma unroll
            for (int r = 0; r < 4; r++) acc[i][j][r] = 0.f;

    const int NK = K >> 5;

    auto issue = [&](int kc, int s) {
        const uint32_t stA = sbase + (uint32_t)(s * 2) * TILE_F * 4u;
        const uint32_t stB = stA + TILE_F * 4u;
        const float* ap = aptr + (size_t)kc * 32;
        const float* bp = bptr + (size_t)kc * 32;
        #pragma unroll
        for (int t = 0; t < 4; t++) {
            const uint32_t so = soff0 + (uint32_t)(t * 32 * LDS36) * 4u;
            cp16(stA + so, ap + (size_t)(t * 32) * K);
            cp16(stB + so, bp + (size_t)(t * 32) * K);
        }
    };

    issue(0, 0); CP_COMMIT();
    issue(1, 1); CP_COMMIT();

    int s_rd = 0, s_wr = 2;
    for (int k = 0; k < NK; k++) {
        CP_WAIT(1);
        __syncthreads();
        if (k + 2 < NK) issue(k + 2, s_wr);
        CP_COMMIT();
        s_wr = (s_wr == STAGES - 1) ? 0 : s_wr + 1;

        const uint32_t sA = sbase + (uint32_t)(s_rd * 2) * TILE_F * 4u;
        const uint32_t sB = sA + TILE_F * 4u;
        s_rd = (s_rd == STAGES - 1) ? 0 : s_rd + 1;

        #pragma unroll
        for (int ks = 0; ks < 4; ks++) {
            uint32_t afr[2][4], bfr4[4][4];
            ldsm_x4(afr[0], sA + aoff + (uint32_t)ks * 32u);
            ldsm_x4(afr[1], sA + aoff + (uint32_t)(16 * LDS36 * 4) + (uint32_t)ks * 32u);
            #pragma unroll
            for (int p = 0; p < 4; p++)
                ldsm_x4(bfr4[p], sB + boff + (uint32_t)(16 * p * LDS36 * 4) + (uint32_t)ks * 32u);
            #pragma unroll
            for (int im = 0; im < 2; im++)
                #pragma unroll
                for (int p = 0; p < 4; p++) {
                    mma_tf32(acc[im][2 * p],     afr[im], &bfr4[p][0]);
                    mma_tf32(acc[im][2 * p + 1], afr[im], &bfr4[p][2]);
                }
        }
    }

    #pragma unroll
    for (int im = 0; im < 2; im++) {
        #pragma unroll
        for (int half = 0; half < 2; half++) {
            const int row = bm + warp_m * 32 + im * 16 + g + half * 8;
            #pragma unroll
            for (int in = 0; in < 8; in++) {
                const int col = bn + warp_n * 64 + in * 8 + 2 * c;
                float v0 = acc[im][in][half * 2 + 0] + bias[col];
                float v1 = acc[im][in][half * 2 + 1] + bias[col + 1];
                if (EPI == 1) {
                    const float2 rr = *reinterpret_cast<const float2*>(
                        &res[(size_t)row * N + col]);
                    v0 += rr.x; v1 += rr.y;
                }
                if (EPI == 2) {
                    v0 = 0.5f * v0 * (1.0f + erff(v0 * 0.70710678118654752f));
                    v1 = 0.5f * v1 * (1.0f + erff(v1 * 0.70710678118654752f));
                }
                float2 o2 = make_float2(v0, v1);
                *reinterpret_cast<float2*>(&C[(size_t)row * N + col]) = o2;
            }
        }
    }
}

template<int EPI>
__global__ __launch_bounds__(256, 2) void tgemm(
    const float* __restrict__ A, const float* __restrict__ Bt,
    const float* __restrict__ bias, const float* __restrict__ res,
    float* __restrict__ C, int M, int N, int K)
{
    tgemm_core<EPI>(A, Bt, bias, res, C, M, N, K,
                    blockIdx.y * 128, blockIdx.x * 128);
}

__global__ __launch_bounds__(256, 2) void tgemm_qkv(
    const float* __restrict__ A,
    const float* __restrict__ wqT, const float* __restrict__ wkT,
    const float* __restrict__ wvT,
    const float* __restrict__ bq, const float* __restrict__ bk,
    const float* __restrict__ bv,
    float* __restrict__ Q, float* __restrict__ Ko, float* __restrict__ V)
{
    const int z = blockIdx.z;
    const float* Bt   = (z == 0) ? wqT : (z == 1) ? wkT : wvT;
    const float* bias = (z == 0) ? bq  : (z == 1) ? bk  : bv;
    float* C          = (z == 0) ? Q   : (z == 1) ? Ko  : V;
    tgemm_core<0>(A, Bt, bias, nullptr, C, MROWS, DD, DD,
                  blockIdx.y * 128, blockIdx.x * 128);
}

// ---------------- block-sparse attention, 4x4 register blocking ------------
// One CTA per (b,h,block). 256 threads: thread (rowg,colg) owns a 4x4 tile.
// Phase 1: S = (Q*scale) K^T, softmax rows via half-warp shfl.
// Phase 2: O = W V (W staged through the Q smem buffer).
#define APS 68   // padded row stride (floats); 16B-aligned float4 rows
__global__ __launch_bounds__(256) void attention_kernel(
    const float* __restrict__ Q, const float* __restrict__ K,
    const float* __restrict__ V, float* __restrict__ O,
    float* __restrict__ W)
{
    __shared__ float qs[64 * APS];   // Q, then reused for softmax weights
    __shared__ float ks[64 * APS];   // K, then reused for V
    const int tid  = threadIdx.x;
    const int rowg = tid >> 4;        // 0..15 (4 rows each)
    const int colg = tid & 15;        // 0..15 (4 cols each)
    const int blk = blockIdx.x;       // b*512 + h*32 + n
    const int n = blk & 31, hh = (blk >> 5) & 15, b = blk >> 9;
    const size_t base = ((size_t)(b * SS + n * 64)) * DD + hh * 64;

    // load Q (scaled) and K: 1024 float4 each, 4 per thread
    #pragma unroll
    for (int t = 0; t < 4; t++) {
        const int idx = tid + t * 256;
        const int r = idx >> 4, c4 = (idx & 15) << 2;
        float4 qv = *reinterpret_cast<const float4*>(&Q[base + (size_t)r * DD + c4]);
        qv.x *= 0.125f; qv.y *= 0.125f; qv.z *= 0.125f; qv.w *= 0.125f;
        *reinterpret_cast<float4*>(&qs[r * APS + c4]) = qv;
        *reinterpret_cast<float4*>(&ks[r * APS + c4]) =
            *reinterpret_cast<const float4*>(&K[base + (size_t)r * DD + c4]);
    }
    __syncthreads();

    // ---- phase 1: scores ----
    float acc[4][4];
    #pragma unroll
    for (int i = 0; i < 4; i++)
        #pragma unroll
        for (int j = 0; j < 4; j++) acc[i][j] = 0.f;

    #pragma unroll
    for (int d4 = 0; d4 < 16; d4++) {
        float4 qv[4], kv[4];
        #pragma unroll
        for (int i = 0; i < 4; i++)
            qv[i] = *reinterpret_cast<const float4*>(&qs[(rowg * 4 + i) * APS + d4 * 4]);
        #pragma unroll
        for (int j = 0; j < 4; j++)
            kv[j] = *reinterpret_cast<const float4*>(&ks[(colg * 4 + j) * APS + d4 * 4]);
        #pragma unroll
        for (int i = 0; i < 4; i++)
            #pragma unroll
            for (int j = 0; j < 4; j++)
                acc[i][j] = fmaf(qv[i].x, kv[j].x,
                            fmaf(qv[i].y, kv[j].y,
                            fmaf(qv[i].z, kv[j].z,
                            fmaf(qv[i].w, kv[j].w, acc[i][j]))));
    }

    // ---- softmax over each row (16 threads per row, half-warp) ----
    float w[4][4];
    #pragma unroll
    for (int i = 0; i < 4; i++) {
        float m = fmaxf(fmaxf(acc[i][0], acc[i][1]), fmaxf(acc[i][2], acc[i][3]));
        #pragma unroll
        for (int o = 8; o; o >>= 1)
            m = fmaxf(m, __shfl_xor_sync(0xffffffffu, m, o));
        float s = 0.f;
        #pragma unroll
        for (int j = 0; j < 4; j++) { w[i][j] = __expf(acc[i][j] - m); s += w[i][j]; }
        #pragma unroll
        for (int o = 8; o; o >>= 1)
            s += __shfl_xor_sync(0xffffffffu, s, o);
        const float inv = 1.0f / s;
        #pragma unroll
        for (int j = 0; j < 4; j++) w[i][j] *= inv;
    }

    // write attn weights to global output (if requested)
    if (W) {
        float* wout = W + (size_t)blk * 4096;
        #pragma unroll
        for (int i = 0; i < 4; i++)
            *reinterpret_cast<float4*>(&wout[(rowg * 4 + i) * 64 + colg * 4]) =
                make_float4(w[i][0], w[i][1], w[i][2], w[i][3]);
    }

    __syncthreads();  // everyone done reading qs/ks
    // stage W into qs; load V into ks
    #pragma unroll
    for (int i = 0; i < 4; i++)
        *reinterpret_cast<float4*>(&qs[(rowg * 4 + i) * APS + colg * 4]) =
            make_float4(w[i][0], w[i][1], w[i][2], w[i][3]);
    #pragma unroll
    for (int t = 0; t < 4; t++) {
        const int idx = tid + t * 256;
        const int r = idx >> 4, c4 = (idx & 15) << 2;
        *reinterpret_cast<float4*>(&ks[r * APS + c4]) =
            *reinterpret_cast<const float4*>(&V[base + (size_t)r * DD + c4]);
    }
    __syncthreads();

    // ---- phase 2: O = W V ----
    float4 oacc[4];
    #pragma unroll
    for (int i = 0; i < 4; i++) oacc[i] = make_float4(0.f, 0.f, 0.f, 0.f);

    #pragma unroll
    for (int j4 = 0; j4 < 16; j4++) {
        float4 wv[4];
        #pragma unroll
        for (int i = 0; i < 4; i++)
            wv[i] = *reinterpret_cast<const float4*>(&qs[(rowg * 4 + i) * APS + j4 * 4]);
        float4 vv[4];
        #pragma unroll
        for (int jj = 0; jj < 4; jj++)
            vv[jj] = *reinterpret_cast<const float4*>(&ks[(j4 * 4 + jj) * APS + colg * 4]);
        #pragma unroll
        for (int i = 0; i < 4; i++) {
            const float* wp = reinterpret_cast<const float*>(&wv[i]);
            #pragma unroll
            for (int jj = 0; jj < 4; jj++) {
                oacc[i].x = fmaf(wp[jj], vv[jj].x, oacc[i].x);
                oacc[i].y = fmaf(wp[jj], vv[jj].y, oacc[i].y);
                oacc[i].z = fmaf(wp[jj], vv[jj].z, oacc[i].z);
                oacc[i].w = fmaf(wp[jj], vv[jj].w, oacc[i].w);
            }
        }
    }

    #pragma unroll
    for (int i = 0; i < 4; i++)
        *reinterpret_cast<float4*>(&O[base + (size_t)(rowg * 4 + i) * DD + colg * 4]) = oacc[i];
}

// ---------------- host launcher ---------------------------------------------
extern "C" void kernel_launch(void* const* d_in, const int* in_sizes, int n_in,
                              void* d_out, int out_size)
{
    const float* hidden = (const float*)d_in[0];
    const float* ln1_g  = (const float*)d_in[1];
    const float* ln1_b  = (const float*)d_in[2];
    const float* ln2_g  = (const float*)d_in[3];
    const float* ln2_b  = (const float*)d_in[4];
    const float* wq = (const float*)d_in[5];  const float* bq = (const float*)d_in[6];
    const float* wk = (const float*)d_in[7];  const float* bk = (const float*)d_in[8];
    const float* wv = (const float*)d_in[9];  const float* bv = (const float*)d_in[10];
    const float* wo = (const float*)d_in[11]; const float* bo = (const float*)d_in[12];
    const float* w1 = (const float*)d_in[13]; const float* b1 = (const float*)d_in[14];
    const float* w2 = (const float*)d_in[15]; const float* b2 = (const float*)d_in[16];
    float* out = (float*)d_out;

    float *x1, *q, *k, *v, *h, *ff;
    float *wqT, *wkT, *wvT, *woT, *w1T, *w2T;
    cudaGetSymbolAddress((void**)&x1, g_x1);
    cudaGetSymbolAddress((void**)&q,  g_q);
    cudaGetSymbolAddress((void**)&k,  g_k);
    cudaGetSymbolAddress((void**)&v,  g_v);
    cudaGetSymbolAddress((void**)&h,  g_h);
    cudaGetSymbolAddress((void**)&ff, g_ff);
    cudaGetSymbolAddress((void**)&wqT, g_wqT);
    cudaGetSymbolAddress((void**)&wkT, g_wkT);
    cudaGetSymbolAddress((void**)&wvT, g_wvT);
    cudaGetSymbolAddress((void**)&woT, g_woT);
    cudaGetSymbolAddress((void**)&w1T, g_w1T);
    cudaGetSymbolAddress((void**)&w2T, g_w2T);

    cudaFuncSetAttribute(tgemm<0>, cudaFuncAttributeMaxDynamicSharedMemorySize, SMEM_BYTES);
    cudaFuncSetAttribute(tgemm<1>, cudaFuncAttributeMaxDynamicSharedMemorySize, SMEM_BYTES);
    cudaFuncSetAttribute(tgemm<2>, cudaFuncAttributeMaxDynamicSharedMemorySize, SMEM_BYTES);
    cudaFuncSetAttribute(tgemm_qkv, cudaFuncAttributeMaxDynamicSharedMemorySize, SMEM_BYTES);

    const int MAIN_ELEMS = MROWS * DD;                 // 8388608
    const int ATTW_ELEMS = BB * HH * NBLK * 64 * 64;   // 8388608
    float* attw = (out_size >= MAIN_ELEMS + ATTW_ELEMS) ? out + MAIN_ELEMS
                                                        : nullptr;

    dim3 tb(32, 8);
    dim3 gD(DD / 128, MROWS / 128);          // (8, 64)
    dim3 gQKV(DD / 128, MROWS / 128, 3);     // (8, 64, 3)
    dim3 gF(FF / 128, MROWS / 128);          // (32, 64)

    // 0: x1 = LN1(hidden)
    ln_kernel<<<MROWS, 256>>>(hidden, ln1_g, ln1_b, x1);
    // 1: transpose QKV weights
    transposeA_kernel<<<3072, tb>>>(wq, wk, wv, wqT, wkT, wvT);
    // 2: q/k/v = x1 @ w{q,k,v} + b (fused, grid.z)
    tgemm_qkv<<<gQKV, 256, SMEM_BYTES>>>(x1, wqT, wkT, wvT, bq, bk, bv, q, k, v);
    // 3: block attention: O into x1; optional attn_w out
    attention_kernel<<<BB * HH * NBLK, 256>>>(q, k, v, x1, attw);
    // 4: transpose wo/w1/w2
    transposeB_kernel<<<9216, tb>>>(wo, w1, w2, woT, w1T, w2T);
    // 5: h = hidden + O @ wo + bo
    tgemm<1><<<gD, 256, SMEM_BYTES>>>(x1, woT, bo, hidden, h, MROWS, DD, DD);
    // 6: x2 = LN2(h)  (into q, reuse)
    ln_kernel<<<MROWS, 256>>>(h, ln2_g, ln2_b, q);
    // 7: ff = gelu(x2 @ w1 + b1)
    tgemm<2><<<gF, 256, SMEM_BYTES>>>(q, w1T, b1, nullptr, ff, MROWS, FF, DD);
    // 8: out = h + ff @ w2 + b2
    tgemm<1><<<gD, 256, SMEM_BYTES>>>(ff, w2T, b2, h, out, MROWS, DD, FF);
}